// round 9
// baseline (speedup 1.0000x reference)
#include <cuda_runtime.h>
#include <cstdint>

#define B_ 4
#define S_ 2048
#define D_ 1024
#define H_ 16
#define DK_ 64
#define DV_ 64
#define DOUT_ 1024

// Scratch: qh/kh/vh in (b,h,s,e) layout; concat in (b,s,h*DV) layout.
// All hold tf32-rounded values (valid fp32 with truncated mantissa).
__device__ float g_qh[(size_t)B_*H_*S_*DK_];
__device__ float g_kh[(size_t)B_*H_*S_*DK_];
__device__ float g_vh[(size_t)B_*H_*S_*DV_];
__device__ float g_cat[(size_t)B_*S_*H_*DV_];

// Pre-converted (tf32-bit) copies of inputs/weights.
__device__ float g_q32[(size_t)B_*S_*D_];
__device__ float g_k32[(size_t)B_*S_*D_];
__device__ float g_v32[(size_t)B_*S_*D_];
__device__ float g_wq32[(size_t)H_*D_*DK_];   // pre-scaled by 0.125*log2(e)
__device__ float g_wk32[(size_t)H_*D_*DK_];
__device__ float g_wv32[(size_t)H_*D_*DV_];
__device__ float g_wo32[(size_t)DOUT_*DOUT_];

// ---------------------------------------------------------------------------
// PTX helpers
// ---------------------------------------------------------------------------
__device__ __forceinline__ uint32_t f2tf(float f) {
    uint32_t u;
    asm("cvt.rna.tf32.f32 %0, %1;" : "=r"(u) : "f"(f));
    return u;
}

__device__ __forceinline__ void mma_tf32(float* d, const uint32_t* a, const uint32_t* b) {
    asm volatile(
        "mma.sync.aligned.m16n8k8.row.col.f32.tf32.tf32.f32 "
        "{%0,%1,%2,%3}, {%4,%5,%6,%7}, {%8,%9}, {%0,%1,%2,%3};\n"
        : "+f"(d[0]), "+f"(d[1]), "+f"(d[2]), "+f"(d[3])
        : "r"(a[0]), "r"(a[1]), "r"(a[2]), "r"(a[3]), "r"(b[0]), "r"(b[1]));
}

__device__ __forceinline__ void cpa16(uint32_t dst, const void* src) {
    asm volatile("cp.async.cg.shared.global [%0], [%1], 16;\n" :: "r"(dst), "l"(src));
}
__device__ __forceinline__ void cpa_commit() {
    asm volatile("cp.async.commit_group;\n");
}
template <int N>
__device__ __forceinline__ void cpa_wait() {
    asm volatile("cp.async.wait_group %0;\n" :: "n"(N));
}

#define QSCALE (0.125f * 1.4426950408889634f)

// ---------------------------------------------------------------------------
// Prep kernels: one-time tf32 conversion (and Q-scale folding into Wq).
// ---------------------------------------------------------------------------
__global__ __launch_bounds__(256) void prep_qkv(
    const float* __restrict__ q, const float* __restrict__ k, const float* __restrict__ v)
{
    const int z = blockIdx.y;
    const float* s = (z == 0) ? q : (z == 1) ? k : v;
    float* d       = (z == 0) ? g_q32 : (z == 1) ? g_k32 : g_v32;
    const size_t i = ((size_t)blockIdx.x * 256 + threadIdx.x) * 4;
    float4 v4 = *(const float4*)(s + i);
    uint4 u;
    u.x = f2tf(v4.x); u.y = f2tf(v4.y); u.z = f2tf(v4.z); u.w = f2tf(v4.w);
    *(uint4*)(d + i) = u;
}

__global__ __launch_bounds__(256) void prep_w(
    const float* __restrict__ Wq, const float* __restrict__ Wk,
    const float* __restrict__ Wv, const float* __restrict__ Wo)
{
    const int z = blockIdx.y;
    const float* s = (z == 0) ? Wq : (z == 1) ? Wk : (z == 2) ? Wv : Wo;
    float* d       = (z == 0) ? g_wq32 : (z == 1) ? g_wk32 : (z == 2) ? g_wv32 : g_wo32;
    const float sc = (z == 0) ? QSCALE : 1.0f;
    const size_t i = ((size_t)blockIdx.x * 256 + threadIdx.x) * 4;
    float4 v4 = *(const float4*)(s + i);
    uint4 u;
    u.x = f2tf(v4.x * sc); u.y = f2tf(v4.y * sc);
    u.z = f2tf(v4.z * sc); u.w = f2tf(v4.w * sc);
    *(uint4*)(d + i) = u;
}

// GEMM smem row strides (floats): A 16+4 pad, B 128+8 pad (bank-conflict-free).
#define AP 20
#define BP 136

// Compute one BK=16 buffer, NO conversions (operands pre-tf32).
__device__ __forceinline__ void mma_compute16_nc(const uint32_t* As, const uint32_t* Bs,
                                                 float acc[4][4][4],
                                                 int wm, int wn, int g, int tig)
{
#pragma unroll
    for (int ks = 0; ks < 2; ++ks) {
        const int kr = ks * 8;
        uint32_t a[4][4];
#pragma unroll
        for (int mf = 0; mf < 4; ++mf) {
            const int m = wm * 64 + mf * 16;
            a[mf][0] = As[(m + g)     * AP + kr + tig];
            a[mf][1] = As[(m + g + 8) * AP + kr + tig];
            a[mf][2] = As[(m + g)     * AP + kr + tig + 4];
            a[mf][3] = As[(m + g + 8) * AP + kr + tig + 4];
        }
        uint32_t b[4][2];
#pragma unroll
        for (int nf = 0; nf < 4; ++nf) {
            const int n = wn * 32 + nf * 8 + g;
            b[nf][0] = Bs[(kr + tig)     * BP + n];
            b[nf][1] = Bs[(kr + tig + 4) * BP + n];
        }
#pragma unroll
        for (int mf = 0; mf < 4; ++mf)
#pragma unroll
            for (int nf = 0; nf < 4; ++nf)
                mma_tf32(acc[mf][nf], a[mf], b[nf]);
    }
}

// ---------------------------------------------------------------------------
// Kernel 1: per-head projections via tf32 mma (pre-converted operands).
// Block tile: 128 rows x 128 cols (2 heads), K=1024, BK=16, double-buffered.
// Epilogue writes tf32-rounded outputs (consumed by attention without cvt).
// ---------------------------------------------------------------------------
__global__ __launch_bounds__(256, 2) void proj_mma(
    const float* __restrict__ bq, const float* __restrict__ bk, const float* __restrict__ bv)
{
    const int z = blockIdx.z;
    const float* X    = (z == 0) ? g_q32  : (z == 1) ? g_k32  : g_v32;
    const float* W    = (z == 0) ? g_wq32 : (z == 1) ? g_wk32 : g_wv32;
    const float* bias = (z == 0) ? bq : (z == 1) ? bk : bv;
    const float bscale = (z == 0) ? QSCALE : 1.0f;
    float* Out        = (z == 0) ? g_qh : (z == 1) ? g_kh : g_vh;

    const int h0 = blockIdx.y * 2;
    const int m0 = blockIdx.x * 128;
    const int b  = m0 >> 11;
    const int s0 = m0 & (S_ - 1);

    const float* Xb = X + (size_t)m0 * D_;

    __shared__ float As[2][128 * AP];
    __shared__ float Bs[2][16 * BP];

    const int tid = threadIdx.x;
    const int wid = tid >> 5, lane = tid & 31;
    const int wm = wid >> 2, wn = wid & 3;
    const int g = lane >> 2, tig = lane & 3;

    const int am = tid >> 1, aj = (tid & 1) * 8;
    const int brow = tid >> 4, bcb = (tid & 15) * 8;
    const float* bsrc0 = W + (size_t)(h0 + (bcb >> 6)) * (D_ * DK_) + (bcb & 63);

    uint32_t aDst[2], bDst[2];
    aDst[0] = (uint32_t)__cvta_generic_to_shared(&As[0][am * AP + aj]);
    aDst[1] = (uint32_t)__cvta_generic_to_shared(&As[1][am * AP + aj]);
    bDst[0] = (uint32_t)__cvta_generic_to_shared(&Bs[0][brow * BP + bcb]);
    bDst[1] = (uint32_t)__cvta_generic_to_shared(&Bs[1][brow * BP + bcb]);

    float acc[4][4][4] = {};

    {
        const float* as = Xb + (size_t)am * D_ + aj;
        cpa16(aDst[0], as);
        cpa16(aDst[0] + 16, as + 4);
        const float* bs = bsrc0 + (size_t)brow * DK_;
        cpa16(bDst[0], bs);
        cpa16(bDst[0] + 16, bs + 4);
        cpa_commit();
    }

    const int NT = D_ / 16;
#pragma unroll 1
    for (int t = 0; t < NT; ++t) {
        if (t + 1 < NT) {
            const int kk = (t + 1) * 16;
            const int bi = (t + 1) & 1;
            const float* as = Xb + (size_t)am * D_ + kk + aj;
            cpa16(aDst[bi], as);
            cpa16(aDst[bi] + 16, as + 4);
            const float* bs = bsrc0 + (size_t)(kk + brow) * DK_;
            cpa16(bDst[bi], bs);
            cpa16(bDst[bi] + 16, bs + 4);
            cpa_commit();
            cpa_wait<1>();
        } else {
            cpa_wait<0>();
        }
        __syncthreads();
        mma_compute16_nc((const uint32_t*)As[t & 1], (const uint32_t*)Bs[t & 1],
                         acc, wm, wn, g, tig);
        __syncthreads();
    }

#pragma unroll
    for (int nf = 0; nf < 4; ++nf) {
        const int c = wn * 32 + nf * 8 + tig * 2;
        const int h = h0 + (c >> 6);
        const int e = c & 63;
        const float b0v = bias[h * DK_ + e] * bscale;
        const float b1v = bias[h * DK_ + e + 1] * bscale;
        float* Ob = Out + ((size_t)(b * H_ + h) * S_ + s0) * DK_ + e;
#pragma unroll
        for (int mf = 0; mf < 4; ++mf) {
            const int r = wm * 64 + mf * 16 + g;
            uint2 u0, u1;
            u0.x = f2tf(acc[mf][nf][0] + b0v);
            u0.y = f2tf(acc[mf][nf][1] + b1v);
            u1.x = f2tf(acc[mf][nf][2] + b0v);
            u1.y = f2tf(acc[mf][nf][3] + b1v);
            *(uint2*)(Ob + (size_t)r * DK_) = u0;
            *(uint2*)(Ob + (size_t)(r + 8) * DK_) = u1;
        }
    }
}

// ---------------------------------------------------------------------------
// Kernel 2: tensor-core flash attention.  Q/K/V arrive pre-tf32 (no cvt).
//  - P re-fragmentation via quad shuffles (bit-exact).
//  - K/V/mask double-buffered with cp.async.
// Block: one (b,h), Br=128 (8 warps x 16 rows), Bc=64.
// ---------------------------------------------------------------------------
#define QP 68
#define KP 68
#define VP 72
#define KBUF (64 * KP)
#define VBUF (64 * VP)
#define SM_K (128 * QP)
#define SM_V (SM_K + 2 * KBUF)
#define SM_M (SM_V + 2 * VBUF)
#define SMEM_ATTN ((SM_M + 128) * 4)

__global__ __launch_bounds__(256, 2) void attn_mma(const int* __restrict__ mask)
{
    extern __shared__ float sm[];
    uint32_t* Qs = (uint32_t*)sm;
    uint32_t* Ks = (uint32_t*)(sm + SM_K);
    uint32_t* Vs = (uint32_t*)(sm + SM_V);
    int*      Ms = (int*)(sm + SM_M);

    const int bh = blockIdx.y;
    const int b = bh >> 4, h = bh & 15;
    const int q0 = blockIdx.x * 128;

    const float* Qg = g_qh + ((size_t)bh * S_ + q0) * DK_;
    const float* Kg = g_kh + (size_t)bh * S_ * DK_;
    const float* Vg = g_vh + (size_t)bh * S_ * DK_;
    const int* mk = mask + (size_t)b * S_;

    const int tid = threadIdx.x;
    const int w = tid >> 5, lane = tid & 31;
    const int g = lane >> 2, t = lane & 3;
    const int lo = t & 1;
    const int sh = t >> 1, sh2 = sh + 2;

    // Q already scaled by 0.125*log2e and tf32-rounded: plain copy.
    for (int i = tid; i < 512; i += 256) {
        const int row = i >> 2, c4 = (i & 3) * 16;
        *(uint4*)(&Qs[row * QP + c4])      = *(const uint4*)(Qg + (size_t)row * DK_ + c4);
        *(uint4*)(&Qs[row * QP + c4 + 4])  = *(const uint4*)(Qg + (size_t)row * DK_ + c4 + 4);
        *(uint4*)(&Qs[row * QP + c4 + 8])  = *(const uint4*)(Qg + (size_t)row * DK_ + c4 + 8);
        *(uint4*)(&Qs[row * QP + c4 + 12]) = *(const uint4*)(Qg + (size_t)row * DK_ + c4 + 12);
    }

    // prologue: chunk 0 into buffer 0
    {
#pragma unroll
        for (int j = 0; j < 4; ++j) {
            const int idx = tid + j * 256;
            const int row = idx >> 4, c = (idx & 15) * 4;
            cpa16((uint32_t)__cvta_generic_to_shared(&Ks[row * KP + c]),
                  Kg + (size_t)row * DK_ + c);
            cpa16((uint32_t)__cvta_generic_to_shared(&Vs[row * VP + c]),
                  Vg + (size_t)row * DK_ + c);
        }
        if (tid < 16)
            cpa16((uint32_t)__cvta_generic_to_shared(&Ms[tid * 4]), mk + tid * 4);
        cpa_commit();
    }

    float oacc[8][4] = {};
    float mold0 = -1e30f, mold1 = -1e30f;
    float lp0 = 0.0f, lp1 = 0.0f;

    const uint32_t* qbase = Qs + (w * 16 + g) * QP;

    const int NCH = S_ / 64;
#pragma unroll 1
    for (int chunk = 0; chunk < NCH; ++chunk) {
        const int bi = chunk & 1;

        if (chunk + 1 < NCH) {
            const int kc = (chunk + 1) * 64;
            const int bo2 = bi ^ 1;
            uint32_t* kd = Ks + bo2 * KBUF;
            uint32_t* vd = Vs + bo2 * VBUF;
#pragma unroll
            for (int j = 0; j < 4; ++j) {
                const int idx = tid + j * 256;
                const int row = idx >> 4, c = (idx & 15) * 4;
                cpa16((uint32_t)__cvta_generic_to_shared(&kd[row * KP + c]),
                      Kg + (size_t)(kc + row) * DK_ + c);
                cpa16((uint32_t)__cvta_generic_to_shared(&vd[row * VP + c]),
                      Vg + (size_t)(kc + row) * DK_ + c);
            }
            if (tid < 16)
                cpa16((uint32_t)__cvta_generic_to_shared(&Ms[bo2 * 64 + tid * 4]),
                      mk + kc + tid * 4);
            cpa_commit();
            cpa_wait<1>();
        } else {
            cpa_wait<0>();
        }
        __syncthreads();

        const uint32_t* Kb = Ks + bi * KBUF;
        const uint32_t* Vb = Vs + bi * VBUF;
        const int*      Mb = Ms + bi * 64;

        // --- scores: S = Q @ K^T (no conversions) ---
        float sc[8][4] = {};
#pragma unroll
        for (int kb = 0; kb < 8; ++kb) {
            uint32_t a[4];
            const uint32_t* qr = qbase + kb * 8 + t;
            a[0] = qr[0];
            a[1] = qr[8 * QP];
            a[2] = qr[4];
            a[3] = qr[8 * QP + 4];
#pragma unroll
            for (int nf = 0; nf < 8; ++nf) {
                uint32_t bb[2];
                const uint32_t* kr = Kb + (nf * 8 + g) * KP + kb * 8 + t;
                bb[0] = kr[0];
                bb[1] = kr[4];
                mma_tf32(sc[nf], a, bb);
            }
        }

        // --- mask + row max ---
        float tm0 = -1e30f, tm1 = -1e30f;
#pragma unroll
        for (int nf = 0; nf < 8; ++nf) {
            const int ma = Mb[nf * 8 + 2 * t];
            const int mb = Mb[nf * 8 + 2 * t + 1];
            if (!ma) { sc[nf][0] = -1e30f; sc[nf][2] = -1e30f; }
            if (!mb) { sc[nf][1] = -1e30f; sc[nf][3] = -1e30f; }
            tm0 = fmaxf(tm0, fmaxf(sc[nf][0], sc[nf][1]));
            tm1 = fmaxf(tm1, fmaxf(sc[nf][2], sc[nf][3]));
        }
        tm0 = fmaxf(tm0, __shfl_xor_sync(0xffffffffu, tm0, 1));
        tm0 = fmaxf(tm0, __shfl_xor_sync(0xffffffffu, tm0, 2));
        tm1 = fmaxf(tm1, __shfl_xor_sync(0xffffffffu, tm1, 1));
        tm1 = fmaxf(tm1, __shfl_xor_sync(0xffffffffu, tm1, 2));

        const float mn0 = fmaxf(mold0, tm0);
        const float mn1 = fmaxf(mold1, tm1);
        const float f0 = exp2f(mold0 - mn0);
        const float f1 = exp2f(mold1 - mn1);
        mold0 = mn0; mold1 = mn1;

        // --- exp + partial sums; overwrite sc with tf32 bits of P ---
        float cs0 = 0.0f, cs1 = 0.0f;
#pragma unroll
        for (int nf = 0; nf < 8; ++nf) {
            const float p0 = exp2f(sc[nf][0] - mn0);
            const float p1 = exp2f(sc[nf][1] - mn0);
            const float p2 = exp2f(sc[nf][2] - mn1);
            const float p3 = exp2f(sc[nf][3] - mn1);
            cs0 += p0 + p1;
            cs1 += p2 + p3;
            sc[nf][0] = __uint_as_float(f2tf(p0));
            sc[nf][1] = __uint_as_float(f2tf(p1));
            sc[nf][2] = __uint_as_float(f2tf(p2));
            sc[nf][3] = __uint_as_float(f2tf(p3));
        }
        lp0 = lp0 * f0 + cs0;
        lp1 = lp1 * f1 + cs1;

#pragma unroll
        for (int nf = 0; nf < 8; ++nf) {
            oacc[nf][0] *= f0; oacc[nf][1] *= f0;
            oacc[nf][2] *= f1; oacc[nf][3] *= f1;
        }

        // --- O += P @ V ; C-frag -> A-frag via quad shuffles ---
#pragma unroll
        for (int kb = 0; kb < 8; ++kb) {
            const uint32_t u0 = __float_as_uint(sc[kb][0]);
            const uint32_t u1 = __float_as_uint(sc[kb][1]);
            const uint32_t u2 = __float_as_uint(sc[kb][2]);
            const uint32_t u3 = __float_as_uint(sc[kb][3]);
            uint32_t a[4];
            {
                const uint32_t x0 = __shfl_sync(0xffffffffu, u0, sh, 4);
                const uint32_t x1 = __shfl_sync(0xffffffffu, u1, sh, 4);
                a[0] = lo ? x1 : x0;
                const uint32_t x2 = __shfl_sync(0xffffffffu, u2, sh, 4);
                const uint32_t x3 = __shfl_sync(0xffffffffu, u3, sh, 4);
                a[1] = lo ? x3 : x2;
                const uint32_t y0 = __shfl_sync(0xffffffffu, u0, sh2, 4);
                const uint32_t y1 = __shfl_sync(0xffffffffu, u1, sh2, 4);
                a[2] = lo ? y1 : y0;
                const uint32_t y2 = __shfl_sync(0xffffffffu, u2, sh2, 4);
                const uint32_t y3 = __shfl_sync(0xffffffffu, u3, sh2, 4);
                a[3] = lo ? y3 : y2;
            }
#pragma unroll
            for (int nf = 0; nf < 8; ++nf) {
                uint32_t bb[2];
                const uint32_t* vr = Vb + (kb * 8 + t) * VP + nf * 8 + g;
                bb[0] = vr[0];
                bb[1] = vr[4 * VP];
                mma_tf32(oacc[nf], a, bb);
            }
        }
        __syncthreads();
    }

    // --- epilogue: quad-reduce l, normalize, write concat as tf32 bits ---
    lp0 += __shfl_xor_sync(0xffffffffu, lp0, 1);
    lp0 += __shfl_xor_sync(0xffffffffu, lp0, 2);
    lp1 += __shfl_xor_sync(0xffffffffu, lp1, 1);
    lp1 += __shfl_xor_sync(0xffffffffu, lp1, 2);
    const float inv0 = 1.0f / lp0;
    const float inv1 = 1.0f / lp1;

    const int r0 = q0 + w * 16 + g;
    float* cat0 = g_cat + ((size_t)b * S_ + r0) * (H_ * DV_) + (size_t)h * DV_;
    float* cat1 = cat0 + (size_t)8 * (H_ * DV_);
#pragma unroll
    for (int nf = 0; nf < 8; ++nf) {
        const int c = nf * 8 + 2 * t;
        uint2 u0, u1;
        u0.x = f2tf(oacc[nf][0] * inv0);
        u0.y = f2tf(oacc[nf][1] * inv0);
        u1.x = f2tf(oacc[nf][2] * inv1);
        u1.y = f2tf(oacc[nf][3] * inv1);
        *(uint2*)(cat0 + c) = u0;
        *(uint2*)(cat1 + c) = u1;
    }
}

// ---------------------------------------------------------------------------
// Kernel 3: output projection via tf32 mma (pre-converted operands).
// ---------------------------------------------------------------------------
__global__ __launch_bounds__(256, 2) void out_mma(
    const float* __restrict__ bo, float* __restrict__ out)
{
    const int m0 = blockIdx.x * 128;
    const int n0 = blockIdx.y * 128;

    const float* Ab = g_cat + (size_t)m0 * DOUT_;

    __shared__ float As[2][128 * AP];
    __shared__ float Bs[2][16 * BP];

    const int tid = threadIdx.x;
    const int wid = tid >> 5, lane = tid & 31;
    const int wm = wid >> 2, wn = wid & 3;
    const int g = lane >> 2, tig = lane & 3;

    const int am = tid >> 1, aj = (tid & 1) * 8;
    const int brow = tid >> 4, bcb = (tid & 15) * 8;
    const float* bsrc0 = g_wo32 + n0 + bcb;

    uint32_t aDst[2], bDst[2];
    aDst[0] = (uint32_t)__cvta_generic_to_shared(&As[0][am * AP + aj]);
    aDst[1] = (uint32_t)__cvta_generic_to_shared(&As[1][am * AP + aj]);
    bDst[0] = (uint32_t)__cvta_generic_to_shared(&Bs[0][brow * BP + bcb]);
    bDst[1] = (uint32_t)__cvta_generic_to_shared(&Bs[1][brow * BP + bcb]);

    float acc[4][4][4] = {};

    {
        const float* as = Ab + (size_t)am * DOUT_ + aj;
        cpa16(aDst[0], as);
        cpa16(aDst[0] + 16, as + 4);
        const float* bs = bsrc0 + (size_t)brow * DOUT_;
        cpa16(bDst[0], bs);
        cpa16(bDst[0] + 16, bs + 4);
        cpa_commit();
    }

    const int NT = DOUT_ / 16;
#pragma unroll 1
    for (int t = 0; t < NT; ++t) {
        if (t + 1 < NT) {
            const int kk = (t + 1) * 16;
            const int bi = (t + 1) & 1;
            const float* as = Ab + (size_t)am * DOUT_ + kk + aj;
            cpa16(aDst[bi], as);
            cpa16(aDst[bi] + 16, as + 4);
            const float* bs = bsrc0 + (size_t)(kk + brow) * DOUT_;
            cpa16(bDst[bi], bs);
            cpa16(bDst[bi] + 16, bs + 4);
            cpa_commit();
            cpa_wait<1>();
        } else {
            cpa_wait<0>();
        }
        __syncthreads();
        mma_compute16_nc((const uint32_t*)As[t & 1], (const uint32_t*)Bs[t & 1],
                         acc, wm, wn, g, tig);
        __syncthreads();
    }

#pragma unroll
    for (int nf = 0; nf < 4; ++nf) {
        const int c = n0 + wn * 32 + nf * 8 + tig * 2;
        const float b0v = bo[c], b1v = bo[c + 1];
#pragma unroll
        for (int mf = 0; mf < 4; ++mf) {
            const int r = m0 + wm * 64 + mf * 16 + g;
            *(float2*)(out + (size_t)r * DOUT_ + c) =
                make_float2(acc[mf][nf][0] + b0v, acc[mf][nf][1] + b1v);
            *(float2*)(out + (size_t)(r + 8) * DOUT_ + c) =
                make_float2(acc[mf][nf][2] + b0v, acc[mf][nf][3] + b1v);
        }
    }
}

// ---------------------------------------------------------------------------
extern "C" void kernel_launch(void* const* d_in, const int* in_sizes, int n_in,
                              void* d_out, int out_size)
{
    const float* q  = (const float*)d_in[0];
    const float* k  = (const float*)d_in[1];
    const float* v  = (const float*)d_in[2];
    const int* mask = (const int*)d_in[3];
    const float* Wq = (const float*)d_in[4];
    const float* bq = (const float*)d_in[5];
    const float* Wk = (const float*)d_in[6];
    const float* bk = (const float*)d_in[7];
    const float* Wv = (const float*)d_in[8];
    const float* bv = (const float*)d_in[9];
    const float* Wo = (const float*)d_in[10];
    const float* bo = (const float*)d_in[11];
    float* out = (float*)d_out;

    cudaFuncSetAttribute(attn_mma, cudaFuncAttributeMaxDynamicSharedMemorySize, SMEM_ATTN);

    // prep: tf32 conversion (Wq/bq pre-scaled inside consumers/prep)
    dim3 gp1((B_ * S_ * D_) / (4 * 256), 3);
    prep_qkv<<<gp1, 256>>>(q, k, v);
    dim3 gp2((H_ * D_ * DK_) / (4 * 256), 4);
    prep_w<<<gp2, 256>>>(Wq, Wk, Wv, Wo);

    dim3 g1((B_ * S_) / 128, H_ / 2, 3);
    proj_mma<<<g1, 256>>>(bq, bk, bv);

    dim3 g2(S_ / 128, B_ * H_);
    attn_mma<<<g2, 256, SMEM_ATTN>>>(mask);

    dim3 g3((B_ * S_) / 128, DOUT_ / 128);
    out_mma<<<g3, 256>>>(bo, out);
}

// round 10
// speedup vs baseline: 1.0911x; 1.0911x over previous
#include <cuda_runtime.h>
#include <cstdint>

#define B_ 4
#define S_ 2048
#define D_ 1024
#define H_ 16
#define DK_ 64
#define DV_ 64
#define DOUT_ 1024

// Scratch: qh/kh/vh in (b,h,s,e) layout (tf32-rounded bits; qh pre-scaled by
// 0.125*log2e); concat in (b,s,h*DV) layout (tf32-rounded).
__device__ float g_qh[(size_t)B_*H_*S_*DK_];
__device__ float g_kh[(size_t)B_*H_*S_*DK_];
__device__ float g_vh[(size_t)B_*H_*S_*DV_];
__device__ float g_cat[(size_t)B_*S_*H_*DV_];

// ---------------------------------------------------------------------------
// PTX helpers
// ---------------------------------------------------------------------------
__device__ __forceinline__ uint32_t f2tf(float f) {
    uint32_t u;
    asm("cvt.rna.tf32.f32 %0, %1;" : "=r"(u) : "f"(f));
    return u;
}

__device__ __forceinline__ void mma_tf32(float* d, const uint32_t* a, const uint32_t* b) {
    asm volatile(
        "mma.sync.aligned.m16n8k8.row.col.f32.tf32.tf32.f32 "
        "{%0,%1,%2,%3}, {%4,%5,%6,%7}, {%8,%9}, {%0,%1,%2,%3};\n"
        : "+f"(d[0]), "+f"(d[1]), "+f"(d[2]), "+f"(d[3])
        : "r"(a[0]), "r"(a[1]), "r"(a[2]), "r"(a[3]), "r"(b[0]), "r"(b[1]));
}

__device__ __forceinline__ void cpa16(uint32_t dst, const void* src) {
    asm volatile("cp.async.cg.shared.global [%0], [%1], 16;\n" :: "r"(dst), "l"(src));
}
__device__ __forceinline__ void cpa_commit() {
    asm volatile("cp.async.commit_group;\n");
}
template <int N>
__device__ __forceinline__ void cpa_wait() {
    asm volatile("cp.async.wait_group %0;\n" :: "n"(N));
}

#define QSCALE (0.125f * 1.4426950408889634f)

// GEMM smem row strides (floats): A 16+4 pad, B 128+8 pad (bank-conflict-free).
#define AP 20
#define BP 136

// Compute one BK=16 buffer with in-loop tf32 cvt (cvt on already-tf32 data is
// an identity, so this is also safe for pre-rounded operands).
__device__ __forceinline__ void mma_compute16(const float* As, const float* Bs,
                                              float acc[4][4][4],
                                              int wm, int wn, int g, int tig)
{
#pragma unroll
    for (int ks = 0; ks < 2; ++ks) {
        const int kr = ks * 8;
        uint32_t a[4][4];
#pragma unroll
        for (int mf = 0; mf < 4; ++mf) {
            const int m = wm * 64 + mf * 16;
            a[mf][0] = f2tf(As[(m + g)     * AP + kr + tig]);
            a[mf][1] = f2tf(As[(m + g + 8) * AP + kr + tig]);
            a[mf][2] = f2tf(As[(m + g)     * AP + kr + tig + 4]);
            a[mf][3] = f2tf(As[(m + g + 8) * AP + kr + tig + 4]);
        }
        uint32_t b[4][2];
#pragma unroll
        for (int nf = 0; nf < 4; ++nf) {
            const int n = wn * 32 + nf * 8 + g;
            b[nf][0] = f2tf(Bs[(kr + tig)     * BP + n]);
            b[nf][1] = f2tf(Bs[(kr + tig + 4) * BP + n]);
        }
#pragma unroll
        for (int mf = 0; mf < 4; ++mf)
#pragma unroll
            for (int nf = 0; nf < 4; ++nf)
                mma_tf32(acc[mf][nf], a[mf], b[nf]);
    }
}

// ---------------------------------------------------------------------------
// Kernel 1: per-head projections via tf32 mma (raw inputs, in-loop cvt).
// Block tile: 128 rows x 128 cols (2 heads), K=1024, BK=16, double-buffered.
// Epilogue writes tf32-rounded outputs; z==0 (Q) additionally pre-scaled by
// QSCALE so the attention kernel needs no scaling or conversion at all.
// ---------------------------------------------------------------------------
__global__ __launch_bounds__(256, 2) void proj_mma(
    const float* __restrict__ q, const float* __restrict__ k, const float* __restrict__ v,
    const float* __restrict__ Wq, const float* __restrict__ Wk, const float* __restrict__ Wv,
    const float* __restrict__ bq, const float* __restrict__ bk, const float* __restrict__ bv)
{
    const int z = blockIdx.z;
    const float* X    = (z == 0) ? q  : (z == 1) ? k  : v;
    const float* W    = (z == 0) ? Wq : (z == 1) ? Wk : Wv;
    const float* bias = (z == 0) ? bq : (z == 1) ? bk : bv;
    const float osc   = (z == 0) ? QSCALE : 1.0f;
    float* Out        = (z == 0) ? g_qh : (z == 1) ? g_kh : g_vh;

    const int h0 = blockIdx.y * 2;
    const int m0 = blockIdx.x * 128;
    const int b  = m0 >> 11;
    const int s0 = m0 & (S_ - 1);

    const float* Xb = X + (size_t)m0 * D_;

    __shared__ float As[2][128 * AP];
    __shared__ float Bs[2][16 * BP];

    const int tid = threadIdx.x;
    const int wid = tid >> 5, lane = tid & 31;
    const int wm = wid >> 2, wn = wid & 3;
    const int g = lane >> 2, tig = lane & 3;

    const int am = tid >> 1, aj = (tid & 1) * 8;
    const int brow = tid >> 4, bcb = (tid & 15) * 8;
    const float* bsrc0 = W + (size_t)(h0 + (bcb >> 6)) * (D_ * DK_) + (bcb & 63);

    uint32_t aDst[2], bDst[2];
    aDst[0] = (uint32_t)__cvta_generic_to_shared(&As[0][am * AP + aj]);
    aDst[1] = (uint32_t)__cvta_generic_to_shared(&As[1][am * AP + aj]);
    bDst[0] = (uint32_t)__cvta_generic_to_shared(&Bs[0][brow * BP + bcb]);
    bDst[1] = (uint32_t)__cvta_generic_to_shared(&Bs[1][brow * BP + bcb]);

    float acc[4][4][4] = {};

    {
        const float* as = Xb + (size_t)am * D_ + aj;
        cpa16(aDst[0], as);
        cpa16(aDst[0] + 16, as + 4);
        const float* bs = bsrc0 + (size_t)brow * DK_;
        cpa16(bDst[0], bs);
        cpa16(bDst[0] + 16, bs + 4);
        cpa_commit();
    }

    const int NT = D_ / 16;
#pragma unroll 1
    for (int t = 0; t < NT; ++t) {
        if (t + 1 < NT) {
            const int kk = (t + 1) * 16;
            const int bi = (t + 1) & 1;
            const float* as = Xb + (size_t)am * D_ + kk + aj;
            cpa16(aDst[bi], as);
            cpa16(aDst[bi] + 16, as + 4);
            const float* bs = bsrc0 + (size_t)(kk + brow) * DK_;
            cpa16(bDst[bi], bs);
            cpa16(bDst[bi] + 16, bs + 4);
            cpa_commit();
            cpa_wait<1>();
        } else {
            cpa_wait<0>();
        }
        __syncthreads();
        mma_compute16(As[t & 1], Bs[t & 1], acc, wm, wn, g, tig);
        __syncthreads();
    }

#pragma unroll
    for (int nf = 0; nf < 4; ++nf) {
        const int c = wn * 32 + nf * 8 + tig * 2;
        const int h = h0 + (c >> 6);
        const int e = c & 63;
        const float b0v = bias[h * DK_ + e];
        const float b1v = bias[h * DK_ + e + 1];
        float* Ob = Out + ((size_t)(b * H_ + h) * S_ + s0) * DK_ + e;
#pragma unroll
        for (int mf = 0; mf < 4; ++mf) {
            const int r = wm * 64 + mf * 16 + g;
            uint2 u0, u1;
            u0.x = f2tf((acc[mf][nf][0] + b0v) * osc);
            u0.y = f2tf((acc[mf][nf][1] + b1v) * osc);
            u1.x = f2tf((acc[mf][nf][2] + b0v) * osc);
            u1.y = f2tf((acc[mf][nf][3] + b1v) * osc);
            *(uint2*)(Ob + (size_t)r * DK_) = u0;
            *(uint2*)(Ob + (size_t)(r + 8) * DK_) = u1;
        }
    }
}

// ---------------------------------------------------------------------------
// Kernel 2: tensor-core flash attention.  Q/K/V arrive pre-tf32 (no cvt),
// Q pre-scaled.  P re-fragmentation via quad shuffles; K/V/mask double-
// buffered with cp.async.  Block: one (b,h), Br=128 (8 warps), Bc=64.
// ---------------------------------------------------------------------------
#define QP 68
#define KP 68
#define VP 72
#define KBUF (64 * KP)
#define VBUF (64 * VP)
#define SM_K (128 * QP)
#define SM_V (SM_K + 2 * KBUF)
#define SM_M (SM_V + 2 * VBUF)
#define SMEM_ATTN ((SM_M + 128) * 4)

__global__ __launch_bounds__(256, 2) void attn_mma(const int* __restrict__ mask)
{
    extern __shared__ float sm[];
    uint32_t* Qs = (uint32_t*)sm;
    uint32_t* Ks = (uint32_t*)(sm + SM_K);
    uint32_t* Vs = (uint32_t*)(sm + SM_V);
    int*      Ms = (int*)(sm + SM_M);

    const int bh = blockIdx.y;
    const int b = bh >> 4, h = bh & 15;
    const int q0 = blockIdx.x * 128;

    const float* Qg = g_qh + ((size_t)bh * S_ + q0) * DK_;
    const float* Kg = g_kh + (size_t)bh * S_ * DK_;
    const float* Vg = g_vh + (size_t)bh * S_ * DK_;
    const int* mk = mask + (size_t)b * S_;

    const int tid = threadIdx.x;
    const int w = tid >> 5, lane = tid & 31;
    const int g = lane >> 2, t = lane & 3;
    const int lo = t & 1;
    const int sh = t >> 1, sh2 = sh + 2;

    // Q already scaled and tf32-rounded: plain vectorized copy.
    for (int i = tid; i < 512; i += 256) {
        const int row = i >> 2, c4 = (i & 3) * 16;
        *(uint4*)(&Qs[row * QP + c4])      = *(const uint4*)(Qg + (size_t)row * DK_ + c4);
        *(uint4*)(&Qs[row * QP + c4 + 4])  = *(const uint4*)(Qg + (size_t)row * DK_ + c4 + 4);
        *(uint4*)(&Qs[row * QP + c4 + 8])  = *(const uint4*)(Qg + (size_t)row * DK_ + c4 + 8);
        *(uint4*)(&Qs[row * QP + c4 + 12]) = *(const uint4*)(Qg + (size_t)row * DK_ + c4 + 12);
    }

    // prologue: chunk 0 into buffer 0
    {
#pragma unroll
        for (int j = 0; j < 4; ++j) {
            const int idx = tid + j * 256;
            const int row = idx >> 4, c = (idx & 15) * 4;
            cpa16((uint32_t)__cvta_generic_to_shared(&Ks[row * KP + c]),
                  Kg + (size_t)row * DK_ + c);
            cpa16((uint32_t)__cvta_generic_to_shared(&Vs[row * VP + c]),
                  Vg + (size_t)row * DK_ + c);
        }
        if (tid < 16)
            cpa16((uint32_t)__cvta_generic_to_shared(&Ms[tid * 4]), mk + tid * 4);
        cpa_commit();
    }

    float oacc[8][4] = {};
    float mold0 = -1e30f, mold1 = -1e30f;
    float lp0 = 0.0f, lp1 = 0.0f;

    const uint32_t* qbase = Qs + (w * 16 + g) * QP;

    const int NCH = S_ / 64;
#pragma unroll 1
    for (int chunk = 0; chunk < NCH; ++chunk) {
        const int bi = chunk & 1;

        if (chunk + 1 < NCH) {
            const int kc = (chunk + 1) * 64;
            const int bo2 = bi ^ 1;
            uint32_t* kd = Ks + bo2 * KBUF;
            uint32_t* vd = Vs + bo2 * VBUF;
#pragma unroll
            for (int j = 0; j < 4; ++j) {
                const int idx = tid + j * 256;
                const int row = idx >> 4, c = (idx & 15) * 4;
                cpa16((uint32_t)__cvta_generic_to_shared(&kd[row * KP + c]),
                      Kg + (size_t)(kc + row) * DK_ + c);
                cpa16((uint32_t)__cvta_generic_to_shared(&vd[row * VP + c]),
                      Vg + (size_t)(kc + row) * DK_ + c);
            }
            if (tid < 16)
                cpa16((uint32_t)__cvta_generic_to_shared(&Ms[bo2 * 64 + tid * 4]),
                      mk + kc + tid * 4);
            cpa_commit();
            cpa_wait<1>();
        } else {
            cpa_wait<0>();
        }
        __syncthreads();

        const uint32_t* Kb = Ks + bi * KBUF;
        const uint32_t* Vb = Vs + bi * VBUF;
        const int*      Mb = Ms + bi * 64;

        // --- scores: S = Q @ K^T (no conversions) ---
        float sc[8][4] = {};
#pragma unroll
        for (int kb = 0; kb < 8; ++kb) {
            uint32_t a[4];
            const uint32_t* qr = qbase + kb * 8 + t;
            a[0] = qr[0];
            a[1] = qr[8 * QP];
            a[2] = qr[4];
            a[3] = qr[8 * QP + 4];
#pragma unroll
            for (int nf = 0; nf < 8; ++nf) {
                uint32_t bb[2];
                const uint32_t* kr = Kb + (nf * 8 + g) * KP + kb * 8 + t;
                bb[0] = kr[0];
                bb[1] = kr[4];
                mma_tf32(sc[nf], a, bb);
            }
        }

        // --- mask + row max ---
        float tm0 = -1e30f, tm1 = -1e30f;
#pragma unroll
        for (int nf = 0; nf < 8; ++nf) {
            const int ma = Mb[nf * 8 + 2 * t];
            const int mb = Mb[nf * 8 + 2 * t + 1];
            if (!ma) { sc[nf][0] = -1e30f; sc[nf][2] = -1e30f; }
            if (!mb) { sc[nf][1] = -1e30f; sc[nf][3] = -1e30f; }
            tm0 = fmaxf(tm0, fmaxf(sc[nf][0], sc[nf][1]));
            tm1 = fmaxf(tm1, fmaxf(sc[nf][2], sc[nf][3]));
        }
        tm0 = fmaxf(tm0, __shfl_xor_sync(0xffffffffu, tm0, 1));
        tm0 = fmaxf(tm0, __shfl_xor_sync(0xffffffffu, tm0, 2));
        tm1 = fmaxf(tm1, __shfl_xor_sync(0xffffffffu, tm1, 1));
        tm1 = fmaxf(tm1, __shfl_xor_sync(0xffffffffu, tm1, 2));

        const float mn0 = fmaxf(mold0, tm0);
        const float mn1 = fmaxf(mold1, tm1);
        const float f0 = exp2f(mold0 - mn0);
        const float f1 = exp2f(mold1 - mn1);
        mold0 = mn0; mold1 = mn1;

        // --- exp + partial sums; overwrite sc with tf32 bits of P ---
        float cs0 = 0.0f, cs1 = 0.0f;
#pragma unroll
        for (int nf = 0; nf < 8; ++nf) {
            const float p0 = exp2f(sc[nf][0] - mn0);
            const float p1 = exp2f(sc[nf][1] - mn0);
            const float p2 = exp2f(sc[nf][2] - mn1);
            const float p3 = exp2f(sc[nf][3] - mn1);
            cs0 += p0 + p1;
            cs1 += p2 + p3;
            sc[nf][0] = __uint_as_float(f2tf(p0));
            sc[nf][1] = __uint_as_float(f2tf(p1));
            sc[nf][2] = __uint_as_float(f2tf(p2));
            sc[nf][3] = __uint_as_float(f2tf(p3));
        }
        lp0 = lp0 * f0 + cs0;
        lp1 = lp1 * f1 + cs1;

#pragma unroll
        for (int nf = 0; nf < 8; ++nf) {
            oacc[nf][0] *= f0; oacc[nf][1] *= f0;
            oacc[nf][2] *= f1; oacc[nf][3] *= f1;
        }

        // --- O += P @ V ; C-frag -> A-frag via quad shuffles (bit-exact) ---
#pragma unroll
        for (int kb = 0; kb < 8; ++kb) {
            const uint32_t u0 = __float_as_uint(sc[kb][0]);
            const uint32_t u1 = __float_as_uint(sc[kb][1]);
            const uint32_t u2 = __float_as_uint(sc[kb][2]);
            const uint32_t u3 = __float_as_uint(sc[kb][3]);
            uint32_t a[4];
            {
                const uint32_t x0 = __shfl_sync(0xffffffffu, u0, sh, 4);
                const uint32_t x1 = __shfl_sync(0xffffffffu, u1, sh, 4);
                a[0] = lo ? x1 : x0;
                const uint32_t x2 = __shfl_sync(0xffffffffu, u2, sh, 4);
                const uint32_t x3 = __shfl_sync(0xffffffffu, u3, sh, 4);
                a[1] = lo ? x3 : x2;
                const uint32_t y0 = __shfl_sync(0xffffffffu, u0, sh2, 4);
                const uint32_t y1 = __shfl_sync(0xffffffffu, u1, sh2, 4);
                a[2] = lo ? y1 : y0;
                const uint32_t y2 = __shfl_sync(0xffffffffu, u2, sh2, 4);
                const uint32_t y3 = __shfl_sync(0xffffffffu, u3, sh2, 4);
                a[3] = lo ? y3 : y2;
            }
#pragma unroll
            for (int nf = 0; nf < 8; ++nf) {
                uint32_t bb[2];
                const uint32_t* vr = Vb + (kb * 8 + t) * VP + nf * 8 + g;
                bb[0] = vr[0];
                bb[1] = vr[4 * VP];
                mma_tf32(oacc[nf], a, bb);
            }
        }
        __syncthreads();
    }

    // --- epilogue: quad-reduce l, normalize, write concat as tf32 bits ---
    lp0 += __shfl_xor_sync(0xffffffffu, lp0, 1);
    lp0 += __shfl_xor_sync(0xffffffffu, lp0, 2);
    lp1 += __shfl_xor_sync(0xffffffffu, lp1, 1);
    lp1 += __shfl_xor_sync(0xffffffffu, lp1, 2);
    const float inv0 = 1.0f / lp0;
    const float inv1 = 1.0f / lp1;

    const int r0 = q0 + w * 16 + g;
    float* cat0 = g_cat + ((size_t)b * S_ + r0) * (H_ * DV_) + (size_t)h * DV_;
    float* cat1 = cat0 + (size_t)8 * (H_ * DV_);
#pragma unroll
    for (int nf = 0; nf < 8; ++nf) {
        const int c = nf * 8 + 2 * t;
        uint2 u0, u1;
        u0.x = f2tf(oacc[nf][0] * inv0);
        u0.y = f2tf(oacc[nf][1] * inv0);
        u1.x = f2tf(oacc[nf][2] * inv1);
        u1.y = f2tf(oacc[nf][3] * inv1);
        *(uint2*)(cat0 + c) = u0;
        *(uint2*)(cat1 + c) = u1;
    }
}

// ---------------------------------------------------------------------------
// Kernel 3: output projection via tf32 mma (A pre-tf32; B raw with in-loop
// cvt — identity on A, real rounding on B).
// ---------------------------------------------------------------------------
__global__ __launch_bounds__(256, 2) void out_mma(
    const float* __restrict__ Wo, const float* __restrict__ bo, float* __restrict__ out)
{
    const int m0 = blockIdx.x * 128;
    const int n0 = blockIdx.y * 128;

    const float* Ab = g_cat + (size_t)m0 * DOUT_;

    __shared__ float As[2][128 * AP];
    __shared__ float Bs[2][16 * BP];

    const int tid = threadIdx.x;
    const int wid = tid >> 5, lane = tid & 31;
    const int wm = wid >> 2, wn = wid & 3;
    const int g = lane >> 2, tig = lane & 3;

    const int am = tid >> 1, aj = (tid & 1) * 8;
    const int brow = tid >> 4, bcb = (tid & 15) * 8;
    const float* bsrc0 = Wo + n0 + bcb;

    uint32_t aDst[2], bDst[2];
    aDst[0] = (uint32_t)__cvta_generic_to_shared(&As[0][am * AP + aj]);
    aDst[1] = (uint32_t)__cvta_generic_to_shared(&As[1][am * AP + aj]);
    bDst[0] = (uint32_t)__cvta_generic_to_shared(&Bs[0][brow * BP + bcb]);
    bDst[1] = (uint32_t)__cvta_generic_to_shared(&Bs[1][brow * BP + bcb]);

    float acc[4][4][4] = {};

    {
        const float* as = Ab + (size_t)am * DOUT_ + aj;
        cpa16(aDst[0], as);
        cpa16(aDst[0] + 16, as + 4);
        const float* bs = bsrc0 + (size_t)brow * DOUT_;
        cpa16(bDst[0], bs);
        cpa16(bDst[0] + 16, bs + 4);
        cpa_commit();
    }

    const int NT = DOUT_ / 16;
#pragma unroll 1
    for (int t = 0; t < NT; ++t) {
        if (t + 1 < NT) {
            const int kk = (t + 1) * 16;
            const int bi = (t + 1) & 1;
            const float* as = Ab + (size_t)am * DOUT_ + kk + aj;
            cpa16(aDst[bi], as);
            cpa16(aDst[bi] + 16, as + 4);
            const float* bs = bsrc0 + (size_t)(kk + brow) * DOUT_;
            cpa16(bDst[bi], bs);
            cpa16(bDst[bi] + 16, bs + 4);
            cpa_commit();
            cpa_wait<1>();
        } else {
            cpa_wait<0>();
        }
        __syncthreads();
        mma_compute16(As[t & 1], Bs[t & 1], acc, wm, wn, g, tig);
        __syncthreads();
    }

#pragma unroll
    for (int nf = 0; nf < 4; ++nf) {
        const int c = n0 + wn * 32 + nf * 8 + tig * 2;
        const float b0v = bo[c], b1v = bo[c + 1];
#pragma unroll
        for (int mf = 0; mf < 4; ++mf) {
            const int r = m0 + wm * 64 + mf * 16 + g;
            *(float2*)(out + (size_t)r * DOUT_ + c) =
                make_float2(acc[mf][nf][0] + b0v, acc[mf][nf][1] + b1v);
            *(float2*)(out + (size_t)(r + 8) * DOUT_ + c) =
                make_float2(acc[mf][nf][2] + b0v, acc[mf][nf][3] + b1v);
        }
    }
}

// ---------------------------------------------------------------------------
extern "C" void kernel_launch(void* const* d_in, const int* in_sizes, int n_in,
                              void* d_out, int out_size)
{
    const float* q  = (const float*)d_in[0];
    const float* k  = (const float*)d_in[1];
    const float* v  = (const float*)d_in[2];
    const int* mask = (const int*)d_in[3];
    const float* Wq = (const float*)d_in[4];
    const float* bq = (const float*)d_in[5];
    const float* Wk = (const float*)d_in[6];
    const float* bk = (const float*)d_in[7];
    const float* Wv = (const float*)d_in[8];
    const float* bv = (const float*)d_in[9];
    const float* Wo = (const float*)d_in[10];
    const float* bo = (const float*)d_in[11];
    float* out = (float*)d_out;

    cudaFuncSetAttribute(attn_mma, cudaFuncAttributeMaxDynamicSharedMemorySize, SMEM_ATTN);

    dim3 g1((B_ * S_) / 128, H_ / 2, 3);
    proj_mma<<<g1, 256>>>(q, k, v, Wq, Wk, Wv, bq, bk, bv);

    dim3 g2(S_ / 128, B_ * H_);
    attn_mma<<<g2, 256, SMEM_ATTN>>>(mask);

    dim3 g3((B_ * S_) / 128, DOUT_ / 128);
    out_mma<<<g3, 256>>>(Wo, bo, out);
}